// round 2
// baseline (speedup 1.0000x reference)
#include <cuda_runtime.h>
#include <math.h>
#include <stdint.h>

#define BB   64
#define NN   8
#define FF   4096
#define H1   1024
#define H2   1024
#define OUTC 512
#define S    (BB*FF)
#define NK   1025
#define MAXEV 26000

__device__ float    g_m[S];
__device__ float    g_s0[H1];
__device__ float    g_bk[H1];
__device__ int      g_bu[H1];
__device__ float    g_alpha[NK*H2];
__device__ float    g_beta [NK*H2];
__device__ float    g_W2T[H2*OUTC];
__device__ int      g_cnt[NK];
__device__ int      g_rank[NK];
__device__ int      g_base[NK];
__device__ int      g_nev;
__device__ unsigned g_mlo_u, g_mhi_u;
__device__ float    g_evm[MAXEV];
__device__ int      g_evp[MAXEV];
__device__ float    g_A2[(size_t)MAXEV*OUTC];
__device__ float    g_C2[(size_t)MAXEV*OUTC];

__device__ __forceinline__ unsigned f2u(float f){
    unsigned u = __float_as_uint(f);
    return (u & 0x80000000u) ? ~u : (u | 0x80000000u);
}
__device__ __forceinline__ float u2f(unsigned e){
    return __uint_as_float((e & 0x80000000u) ? (e & 0x7FFFFFFFu) : ~e);
}

__global__ void k_init(){
    int t = blockIdx.x*1024 + threadIdx.x;
    if (t < NK){ g_cnt[t] = 0; g_rank[t] = 0; }
    if (t == 0){ g_mlo_u = 0xFFFFFFFFu; g_mhi_u = 0u; }
}

__global__ void k_mean(const float* __restrict__ x){
    int s = blockIdx.x*256 + threadIdx.x;
    int b = s >> 12, f = s & 4095;
    const float* xp = x + ((size_t)b*NN)*FF + f;
    float sum = 0.f;
    #pragma unroll
    for (int n = 0; n < NN; n++) sum += xp[(size_t)n*FF];
    float m = sum * (1.0f/NN);
    g_m[s] = m;
    unsigned e = f2u(m);
    __shared__ unsigned smin[256], smax[256];
    int t = threadIdx.x;
    smin[t] = e; smax[t] = e; __syncthreads();
    for (int st = 128; st > 0; st >>= 1){
        if (t < st){
            smin[t] = min(smin[t], smin[t+st]);
            smax[t] = max(smax[t], smax[t+st]);
        }
        __syncthreads();
    }
    if (t == 0){ atomicMin(&g_mlo_u, smin[0]); atomicMax(&g_mhi_u, smax[0]); }
}

__global__ void k_prep(const float* __restrict__ W0, const float* __restrict__ b0){
    int u = blockIdx.x*256 + threadIdx.x;
    if (u >= H1) return;
    float s = 0.f;
    #pragma unroll
    for (int c = 0; c < NN; c++) s += W0[u*NN + c];
    g_s0[u] = s;
    float t;
    if (s != 0.f){
        t = -b0[u] / s;
        if (!isfinite(t)) t = (t > 0.f) ? 3e37f : -3e37f;
    } else t = 3e37f;
    g_bk[u] = t; g_bu[u] = u;
}

__global__ void k_sort(){
    __shared__ float sk[1024];
    __shared__ int   sv[1024];
    int t = threadIdx.x;
    sk[t] = g_bk[t]; sv[t] = g_bu[t];
    __syncthreads();
    for (int size = 2; size <= 1024; size <<= 1){
        for (int stride = size >> 1; stride > 0; stride >>= 1){
            int i = t, j = i ^ stride;
            if (j > i){
                bool up = ((i & size) == 0);
                float ki = sk[i], kj = sk[j];
                int   vi = sv[i], vj = sv[j];
                bool gt = (ki > kj) || (ki == kj && vi > vj);
                if (gt == up){ sk[i]=kj; sk[j]=ki; sv[i]=vj; sv[j]=vi; }
            }
            __syncthreads();
        }
    }
    g_bk[t] = sk[t]; g_bu[t] = sv[t];
}

__global__ void k_tr(const float* __restrict__ W2){
    int idx = blockIdx.x*512 + threadIdx.x;
    int o = idx >> 9, j = idx & 511;
    g_W2T[idx] = W2[(size_t)j*H2 + o];
}

__global__ void k_sweep(const float* __restrict__ W1,
                        const float* __restrict__ b0,
                        const float* __restrict__ b1){
    int o = blockIdx.x*64 + threadIdx.x;
    __shared__ int   s_u[1024];
    __shared__ float s_s0[1024];
    __shared__ float s_b0[1024];
    for (int i = threadIdx.x; i < 1024; i += 64){
        int u = g_bu[i];
        s_u[i] = u; s_s0[i] = g_s0[u]; s_b0[i] = b0[u];
    }
    __syncthreads();
    const float* W1row = W1 + (size_t)o*H1;
    float a = 0.f, bt = 0.f;
    for (int kk = 0; kk < 1024; kk++){
        float s0v = s_s0[kk];
        bool act0 = (s0v < 0.f) || (s0v == 0.f && s_b0[kk] > 0.f);
        if (act0){
            float w = W1row[s_u[kk]];
            a  = fmaf(w, s0v,      a);
            bt = fmaf(w, s_b0[kk], bt);
        }
    }
    bt += b1[o];
    for (int kk = 0; kk < 1024; kk++){
        g_alpha[kk*H2 + o] = a;
        g_beta [kk*H2 + o] = bt;
        float s0v = s_s0[kk];
        float w = W1row[s_u[kk]];
        float sgn = (s0v > 0.f) ? 1.f : ((s0v < 0.f) ? -1.f : 0.f);
        a  = fmaf(sgn*w, s0v,      a);
        bt = fmaf(sgn*w, s_b0[kk], bt);
    }
    g_alpha[1024*H2 + o] = a;
    g_beta [1024*H2 + o] = bt;
}

__global__ void k_count(){
    int k = blockIdx.x;
    int o = blockIdx.y*256 + threadIdx.x;
    float mlo = u2f(g_mlo_u), mhi = u2f(g_mhi_u);
    float tL = (k == 0)    ? -3e38f : g_bk[k-1];
    float tR = (k == 1024) ?  3e38f : g_bk[k];
    float L = fmaxf(tL, mlo), R = fminf(tR, mhi);
    if (!(L < R)) return;
    float a = g_alpha[k*H2 + o], b = g_beta[k*H2 + o];
    bool sL = fmaf(a, L, b) > 0.f;
    bool sR = fmaf(a, R, b) > 0.f;
    if (sL != sR) atomicAdd(&g_cnt[k], 1);
}

__global__ void k_scan(){
    float mlo = u2f(g_mlo_u), mhi = u2f(g_mhi_u);
    int acc = 0;
    for (int k = 0; k < NK; k++){
        g_base[k] = acc;
        int bnd = (k < 1024 && g_bk[k] > mlo && g_bk[k] < mhi) ? 1 : 0;
        acc += g_cnt[k] + bnd;
    }
    if (acc > MAXEV) acc = MAXEV;
    g_nev = acc;
}

__global__ void k_fill(){
    int k = blockIdx.x;
    int o = blockIdx.y*256 + threadIdx.x;
    float mlo = u2f(g_mlo_u), mhi = u2f(g_mhi_u);
    if (blockIdx.y == 0 && threadIdx.x == 0 && k < 1024){
        float t = g_bk[k];
        if (t > mlo && t < mhi){
            int pos = g_base[k] + g_cnt[k];
            if (pos < MAXEV){ g_evm[pos] = t; g_evp[pos] = (1 << 21); }
        }
    }
    float tL = (k == 0)    ? -3e38f : g_bk[k-1];
    float tR = (k == 1024) ?  3e38f : g_bk[k];
    float L = fmaxf(tL, mlo), R = fminf(tR, mhi);
    if (!(L < R)) return;
    float a = g_alpha[k*H2 + o], b = g_beta[k*H2 + o];
    bool sL = fmaf(a, L, b) > 0.f;
    bool sR = fmaf(a, R, b) > 0.f;
    if (sL != sR){
        float ms = -b / a;
        ms = fminf(fmaxf(ms, L), R);
        int rk = atomicAdd(&g_rank[k], 1);
        int pos = g_base[k] + rk;
        if (pos < MAXEV){
            g_evm[pos] = ms;
            g_evp[pos] = o | (sR ? (1 << 20) : 0);
        }
    }
}

__global__ void k_segsort(){
    int k = blockIdx.x*256 + threadIdx.x;
    if (k >= NK) return;
    int s = g_base[k], n = g_cnt[k];
    if (s + n > MAXEV) n = MAXEV - s;
    for (int i = 1; i < n; i++){
        float key = g_evm[s+i]; int p = g_evp[s+i];
        int j = i - 1;
        while (j >= 0 && (g_evm[s+j] > key || (g_evm[s+j] == key && g_evp[s+j] > p))){
            g_evm[s+j+1] = g_evm[s+j]; g_evp[s+j+1] = g_evp[s+j]; j--;
        }
        g_evm[s+j+1] = key; g_evp[s+j+1] = p;
    }
}

__global__ void __launch_bounds__(512) k_chain(const float* __restrict__ b2){
    int k = blockIdx.x;
    float mlo = u2f(g_mlo_u), mhi = u2f(g_mhi_u);
    float tL = (k == 0)    ? -3e38f : g_bk[k-1];
    float tR = (k == 1024) ?  3e38f : g_bk[k];
    float L = fmaxf(tL, mlo), R = fminf(tR, mhi);
    if (!(L < R)) return;
    int r0 = g_base[k];
    int ne = g_cnt[k];
    int NEV = g_nev;
    if (r0 >= MAXEV) return;
    if (r0 + ne >= MAXEV) ne = MAXEV - 1 - r0;

    __shared__ float  s_a[1024];
    __shared__ float  s_b[1024];
    __shared__ float2 s_g[1024];

    float right = (ne > 0) ? g_evm[r0] : R;
    float mid = 0.5f*(L + right);

    for (int o = threadIdx.x; o < 1024; o += 512){
        float av = g_alpha[k*H2 + o];
        float bv = g_beta [k*H2 + o];
        s_a[o] = av; s_b[o] = bv;
        bool act = fmaf(av, mid, bv) > 0.f;
        s_g[o] = act ? make_float2(av, bv) : make_float2(0.f, 0.f);
    }
    __syncthreads();

    int j = threadIdx.x;
    float a2 = 0.f, c2 = b2[j];
    #pragma unroll 8
    for (int o = 0; o < 1024; o++){
        float w = g_W2T[o*OUTC + j];
        float2 g = s_g[o];
        a2 = fmaf(g.x, w, a2);
        c2 = fmaf(g.y, w, c2);
    }
    g_A2[(size_t)r0*OUTC + j] = a2;
    g_C2[(size_t)r0*OUTC + j] = c2;

    for (int e = 0; e < ne; e++){
        int p = g_evp[r0 + e];
        int oo = p & 1023;
        float sgn = (p & (1 << 20)) ? 1.f : -1.f;
        float w = g_W2T[oo*OUTC + j];
        a2 = fmaf(sgn*s_a[oo], w, a2);
        c2 = fmaf(sgn*s_b[oo], w, c2);
        int r = r0 + 1 + e;
        g_A2[(size_t)r*OUTC + j] = a2;
        g_C2[(size_t)r*OUTC + j] = c2;
    }
}

__global__ void __launch_bounds__(128) k_apply(float* __restrict__ out){
    int s = blockIdx.x*128 + threadIdx.x;
    float m = g_m[s];
    int lo = 0, hi = g_nev;
    while (lo < hi){
        int mid = (lo + hi) >> 1;
        if (g_evm[mid] <= m) lo = mid + 1; else hi = mid;
    }
    const float4* A = (const float4*)(g_A2 + (size_t)lo*OUTC);
    const float4* C = (const float4*)(g_C2 + (size_t)lo*OUTC);
    int b = s >> 12, f = s & 4095;
    float* op = out + (size_t)b*OUTC*FF + f;
    #pragma unroll 8
    for (int i = 0; i < OUTC/4; i++){
        float4 av = __ldg(A + i);
        float4 cv = __ldg(C + i);
        op[(size_t)(4*i+0)*FF] = fmaf(m, av.x, cv.x);
        op[(size_t)(4*i+1)*FF] = fmaf(m, av.y, cv.y);
        op[(size_t)(4*i+2)*FF] = fmaf(m, av.z, cv.z);
        op[(size_t)(4*i+3)*FF] = fmaf(m, av.w, cv.w);
    }
}

extern "C" void kernel_launch(void* const* d_in, const int* in_sizes, int n_in,
                              void* d_out, int out_size){
    const float* x  = (const float*)d_in[0];
    const float* W0 = (const float*)d_in[1];
    const float* b0 = (const float*)d_in[2];
    const float* W1 = (const float*)d_in[3];
    const float* b1 = (const float*)d_in[4];
    const float* W2 = (const float*)d_in[5];
    const float* b2 = (const float*)d_in[6];
    float* out = (float*)d_out;

    k_init   <<<2, 1024>>>();
    k_mean   <<<S/256, 256>>>(x);
    k_prep   <<<4, 256>>>(W0, b0);
    k_sort   <<<1, 1024>>>();
    k_tr     <<<H2*OUTC/512, 512>>>(W2);
    k_sweep  <<<H2/64, 64>>>(W1, b0, b1);
    k_count  <<<dim3(NK, 4), 256>>>();
    k_scan   <<<1, 1>>>();
    k_fill   <<<dim3(NK, 4), 256>>>();
    k_segsort<<<(NK+255)/256, 256>>>();
    k_chain  <<<NK, 512>>>(b2);
    k_apply  <<<S/128, 128>>>(out);
}